// round 9
// baseline (speedup 1.0000x reference)
#include <cuda_runtime.h>
#include <cstdint>
#include <type_traits>

namespace {

constexpr int LD   = 9;     // 2*lambd+1
constexpr int NP   = 61;    // valid (mu,m1) / (mup,m1p) pairs
constexpr int BLK  = 64;    // samples per block
constexpr int THR  = 128;   // 2 threads per sample (mu-split)
constexpr int T4   = BLK * 81 / 4;  // 1296 float4 per tile

__host__ __device__ constexpr int imax(int a, int b) { return a > b ? a : b; }
__host__ __device__ constexpr int imin(int a, int b) { return a < b ? a : b; }

__host__ __device__ constexpr int lo_m(int m2) { return imax(0, 4 - m2); }
__host__ __device__ constexpr int hi_m(int m2) { return imin(8, 12 - m2); }

__host__ __device__ constexpr int cntmu(int mu) { return 9 - (mu >= 4 ? mu - 4 : 4 - mu); }
__host__ __device__ constexpr int ofsmu(int mu) {
    int o = 0;
    for (int i = 0; i < mu; i++) o += cntmu(i);
    return o;
}

// pair index p for (m1,m2): mu-major, m1 ascending (matches reference enumeration)
__host__ __device__ constexpr int pidx(int m1, int m2) {
    int mu   = m1 + m2 - 4;
    int m1lo = imax(0, mu - 4);
    return ofsmu(mu) + (m1 - m1lo);
}

__host__ __device__ constexpr int gcnt(int lo, int hi) {
    int c = 0;
    for (int j = lo; j < hi; j++) c += hi_m(j) - lo_m(j) + 1;
    return c;
}
__host__ __device__ constexpr int gpos(int LO, int m2p, int m1p) {
    return gcnt(LO, m2p) + (m1p - lo_m(m2p));
}

template <int S, int E, class F>
__device__ __forceinline__ void static_for(F&& f) {
    if constexpr (S < E) {
        f(std::integral_constant<int, S>{});
        static_for<S + 1, E>(f);
    }
}

__device__ __forceinline__ uint32_t smem_u32(const void* p) {
    uint32_t a;
    asm("{ .reg .u64 t; cvta.to.shared.u64 t, %1; cvt.u32.u64 %0, t; }" : "=r"(a) : "l"(p));
    return a;
}

// 16B async copy, src_size 0 -> zero-fill (branch-free tail handling)
__device__ __forceinline__ void cp16(uint32_t dst, const float4* src, int sz) {
    asm volatile("cp.async.cg.shared.global [%0], [%1], 16, %2;\n"
                 :: "r"(dst), "l"(src), "r"(sz));
}

// One (m2, q-half) pass restricted to mu in [MULO, MUHI].
// Builds g[] for q with m2p in [LO,HI), then accumulates the valid (m1, q)
// FFMAs of this role's mu rows. Everything register-resident.
template <int M2, int LO, int HI, int MULO, int MUHI, int NACC>
__device__ __forceinline__ void half_pass(const float* __restrict__ x1t,
                                          const float (&x2r)[LD],
                                          const float* __restrict__ us,
                                          const float* __restrict__ vs,
                                          float (&acc)[NACC]) {
    constexpr int GN = gcnt(LO, HI);
    float g[GN];
    static_for<LO, HI>([&](auto Jc) {
        constexpr int m2p = decltype(Jc)::value;
        static_for<lo_m(m2p), hi_m(m2p) + 1>([&](auto Ic) {
            constexpr int m1p = decltype(Ic)::value;
            g[gpos(LO, m2p, m1p)] = vs[pidx(m1p, m2p)] * x2r[m2p];
        });
    });
    constexpr int m1lo = imax(lo_m(M2), MULO + 4 - M2);
    constexpr int m1hi = imin(hi_m(M2), MUHI + 4 - M2);
    static_for<m1lo, m1hi + 1>([&](auto Mc) {
        constexpr int m1 = decltype(Mc)::value;
        const float uu = us[pidx(m1, M2)];
        float t[LD];
        static_for<0, LD>([&](auto Kc) {
            constexpr int m1p = decltype(Kc)::value;
            t[m1p] = uu * x1t[m1 * LD + m1p];   // LDS, conflict-free (stride 81, odd)
        });
        static_for<LO, HI>([&](auto Jc) {
            constexpr int m2p = decltype(Jc)::value;
            static_for<lo_m(m2p), hi_m(m2p) + 1>([&](auto Ic) {
                constexpr int m1p = decltype(Ic)::value;
                acc[(m1 + M2 - 4 - MULO) * LD + (m1p + m2p - 4)] +=
                    t[m1p] * g[gpos(LO, m2p, m1p)];
            });
        });
    });
}

// Full compute for one role: mu rows [MULO, MUHI], all 9 X2 rows.
// Writes its disjoint slice of the flat 81-wide output into the staging tile.
template <int MULO, int MUHI>
__device__ __forceinline__ void compute_role(const float* __restrict__ x1t,
                                             const float* __restrict__ x2t,
                                             const float* __restrict__ us,
                                             const float* __restrict__ vs,
                                             float* __restrict__ stage) {
    constexpr int NACC = (MUHI - MULO + 1) * LD;
    float acc[NACC];
#pragma unroll
    for (int i = 0; i < NACC; i++) acc[i] = 0.0f;

    static_for<0, LD>([&](auto M2c) {
        constexpr int m2 = decltype(M2c)::value;
        float x2r[LD];
        static_for<0, LD>([&](auto Jc) {
            constexpr int j = decltype(Jc)::value;
            x2r[j] = x2t[m2 * LD + j];           // conflict-free LDS
        });
        half_pass<m2, 0, 5, MULO, MUHI>(x1t, x2r, us, vs, acc);  // g-halves cap regs
        half_pass<m2, 5, 9, MULO, MUHI>(x1t, x2r, us, vs, acc);
    });

#pragma unroll
    for (int i = 0; i < NACC; i++) stage[MULO * LD + i] = acc[i];
}

__global__ void __launch_bounds__(THR, 4)
wigner_kernel(const float* __restrict__ X1,
              const float* __restrict__ X2,
              const float* __restrict__ mult,
              float* __restrict__ out, int n) {
    __shared__ __align__(16) float x1s[BLK * 81];
    __shared__ __align__(16) float x2s[BLK * 81];
    __shared__ float us[NP];
    __shared__ float vs[NP];

    const int tid    = threadIdx.x;
    const int lane   = tid & (BLK - 1);   // sample within block
    const int role   = tid >> 6;          // 0: mu 0-4 (out 0..44), 1: mu 5-8 (out 45..80)
    const int bstart = blockIdx.x * BLK;

    // Rank-1 refactorization of mult: mult[p*61+q] = c[p]*c[q]
    if (tid < NP) {
        vs[tid] = mult[tid];
        us[tid] = mult[tid * NP] * (1.0f / mult[0]);
    }

    // Stage BOTH tiles via cp.async (independent 16B copies, single wait).
    {
        const int      gbase4 = bstart * 81 / 4;       // bstart*81 % 4 == 0 (BLK=64)
        const int      tot4   = n * 81 / 4;
        const float4*  s1     = reinterpret_cast<const float4*>(X1);
        const float4*  s2     = reinterpret_cast<const float4*>(X2);
        const uint32_t d1     = smem_u32(x1s);
        const uint32_t d2     = smem_u32(x2s);
#pragma unroll
        for (int k = 0; k < (T4 + THR - 1) / THR; k++) {   // 11 slots
            const int idx = k * THR + tid;
            if (idx < T4) {
                const int sz = (gbase4 + idx < tot4) ? 16 : 0;  // tail -> zero-fill
                cp16(d1 + idx * 16, s1 + gbase4 + idx, sz);
                cp16(d2 + idx * 16, s2 + gbase4 + idx, sz);
            }
        }
        asm volatile("cp.async.commit_group;\n");
        asm volatile("cp.async.wait_group 0;\n" ::: "memory");
    }
    __syncthreads();

    // Compute into registers (acc slices are a disjoint partition of out[0..80],
    // so no cross-thread reduction is ever needed).
    float resA[45];  // staged via compute_role writing directly after sync below
    (void)resA;
    {
        const float* __restrict__ x1t = x1s + lane * 81;
        const float* __restrict__ x2t = x2s + lane * 81;
        // Compute first, hold in regs; stage after all readers pass the barrier.
        if (role == 0) {
            float acc[45];
#pragma unroll
            for (int i = 0; i < 45; i++) acc[i] = 0.0f;
            static_for<0, LD>([&](auto M2c) {
                constexpr int m2 = decltype(M2c)::value;
                float x2r[LD];
                static_for<0, LD>([&](auto Jc) {
                    constexpr int j = decltype(Jc)::value;
                    x2r[j] = x2t[m2 * LD + j];
                });
                half_pass<m2, 0, 5, 0, 4>(x1t, x2r, us, vs, acc);
                half_pass<m2, 5, 9, 0, 4>(x1t, x2r, us, vs, acc);
            });
            __syncthreads();   // all compute reads of x1s/x2s done
#pragma unroll
            for (int i = 0; i < 45; i++) x1s[lane * 81 + i] = acc[i];
        } else {
            float acc[36];
#pragma unroll
            for (int i = 0; i < 36; i++) acc[i] = 0.0f;
            static_for<0, LD>([&](auto M2c) {
                constexpr int m2 = decltype(M2c)::value;
                float x2r[LD];
                static_for<0, LD>([&](auto Jc) {
                    constexpr int j = decltype(Jc)::value;
                    x2r[j] = x2t[m2 * LD + j];
                });
                half_pass<m2, 0, 5, 5, 8>(x1t, x2r, us, vs, acc);
                half_pass<m2, 5, 9, 5, 8>(x1t, x2r, us, vs, acc);
            });
            __syncthreads();
#pragma unroll
            for (int i = 0; i < 36; i++) x1s[lane * 81 + 45 + i] = acc[i];
        }
    }
    __syncthreads();

    // Coalesced float4 writeback of the assembled tile.
    {
        const float4* srcs   = reinterpret_cast<const float4*>(x1s);
        float4*       dsto   = reinterpret_cast<float4*>(out);
        const int     gbase4 = bstart * 81 / 4;
        const int     tot4   = n * 81 / 4;
#pragma unroll
        for (int k = 0; k < (T4 + THR - 1) / THR; k++) {
            const int idx = k * THR + tid;
            if (idx < T4 && gbase4 + idx < tot4) dsto[gbase4 + idx] = srcs[idx];
        }
    }
}

}  // namespace

extern "C" void kernel_launch(void* const* d_in, const int* in_sizes, int n_in,
                              void* d_out, int out_size) {
    const float* X1   = (const float*)d_in[0];
    const float* X2   = (const float*)d_in[1];
    const float* mult = (const float*)d_in[6];
    float*       out  = (float*)d_out;

    const int n      = in_sizes[0] / 81;
    const int blocks = (n + BLK - 1) / BLK;
    wigner_kernel<<<blocks, THR>>>(X1, X2, mult, out, n);
}